// round 1
// baseline (speedup 1.0000x reference)
#include <cuda_runtime.h>
#include <cstdint>

// Problem constants (fixed by the reference)
#define B_ 32
#define S_ 512
#define P_ 8
#define K_ 256
#define D_ 64
#define NROWS (B_ * S_ * P_)   // 131072 rows of K=256 logits each

// ---------------------------------------------------------------------------
// JAX threefry2x32, partitionable mode, key = jax.random.key(42) -> (0, 42).
// Per-element 64-bit counter = flat index i (< 2^32, so hi word == 0).
// 32-bit draw = out0 ^ out1.
// ---------------------------------------------------------------------------
__device__ __forceinline__ uint32_t rotl32(uint32_t x, int r) {
    return __funnelshift_l(x, x, r);
}

__device__ __forceinline__ uint32_t threefry_bits(uint32_t i) {
    const uint32_t ks0 = 0u;
    const uint32_t ks1 = 42u;
    const uint32_t ks2 = 0x1BD11BDAu ^ 0u ^ 42u;
    uint32_t x0 = 0u + ks0;   // counts_hi + ks0
    uint32_t x1 = i + ks1;    // counts_lo + ks1
#define TF_ROUND(r) { x0 += x1; x1 = rotl32(x1, (r)) ^ x0; }
    TF_ROUND(13) TF_ROUND(15) TF_ROUND(26) TF_ROUND(6)
    x0 += ks1; x1 += ks2 + 1u;
    TF_ROUND(17) TF_ROUND(29) TF_ROUND(16) TF_ROUND(24)
    x0 += ks2; x1 += ks0 + 2u;
    TF_ROUND(13) TF_ROUND(15) TF_ROUND(26) TF_ROUND(6)
    x0 += ks0; x1 += ks1 + 3u;
    TF_ROUND(17) TF_ROUND(29) TF_ROUND(16) TF_ROUND(24)
    x0 += ks1; x1 += ks2 + 4u;
    TF_ROUND(13) TF_ROUND(15) TF_ROUND(26) TF_ROUND(6)
    x0 += ks2; x1 += ks0 + 5u;
#undef TF_ROUND
    return x0 ^ x1;
}

// jax.random.uniform(minval=tiny) -> gumbel, matching _uniform + _gumbel in fp32
__device__ __forceinline__ float gumbel_from_bits(uint32_t bits) {
    float f = __uint_as_float((bits >> 9) | 0x3f800000u) - 1.0f;  // [0, 1)
    float u = fmaxf(f, 1.17549435e-38f);                          // minval = tiny
    return -logf(-logf(u));
}

// ---------------------------------------------------------------------------
// One warp per (b, s, p) row:
//   cat = inputs[b*S+s]; logits[k] = pattern_map[cat, p, k] + gumbel(flat_idx)
//   k* = argmax (first-max tie-break, matching jnp.argmax)
//   out[row, :] = symbols[k*, :]   (straight-through weights == one_hot to fp32 rounding)
// ---------------------------------------------------------------------------
__global__ void __launch_bounds__(256) symbolic_gumbel_kernel(
    const int*   __restrict__ inputs,       // [B, S] int32
    const float* __restrict__ pattern_map,  // [N_CAT, P, K]
    const float* __restrict__ symbols,      // [K, D]
    float*       __restrict__ out)          // [B, S, P*D]
{
    const int warp = (blockIdx.x * blockDim.x + threadIdx.x) >> 5;
    const int lane = threadIdx.x & 31;
    if (warp >= NROWS) return;

    const int row = warp;
    const int bs  = row >> 3;   // row / P_
    const int p   = row & 7;    // row % P_
    const int cat = __ldg(&inputs[bs]);

    const float* erow = pattern_map + ((size_t)cat * P_ + p) * K_;

    // Each lane owns k in [lane*8, lane*8+8): contiguous float4 loads, and the
    // flat PRNG counter base for this row is row*K_.
    const uint32_t base = (uint32_t)row * (uint32_t)K_ + (uint32_t)(lane * 8);

    const float4* e4 = reinterpret_cast<const float4*>(erow + lane * 8);
    float4 ea = __ldg(&e4[0]);
    float4 eb = __ldg(&e4[1]);
    float e[8] = {ea.x, ea.y, ea.z, ea.w, eb.x, eb.y, eb.z, eb.w};

    float best  = __int_as_float(0xff800000);  // -inf
    int   bestk = 0;
#pragma unroll
    for (int j = 0; j < 8; j++) {
        float g = gumbel_from_bits(threefry_bits(base + (uint32_t)j));
        float x = e[j] + g;
        // strict '>' keeps the first (lowest-k) max within the lane,
        // and k is ascending in j
        if (x > best) { best = x; bestk = lane * 8 + j; }
    }

    // Warp argmax reduction with first-index tie-break
#pragma unroll
    for (int off = 16; off > 0; off >>= 1) {
        float ob = __shfl_xor_sync(0xffffffffu, best, off);
        int   ok = __shfl_xor_sync(0xffffffffu, bestk, off);
        if (ob > best || (ob == best && ok < bestk)) { best = ob; bestk = ok; }
    }
    // all lanes agree on bestk now

    // Copy symbols[bestk, :] (64 floats = 256B) to out[row, :], 2 floats/lane
    const float2* srow = reinterpret_cast<const float2*>(symbols + (size_t)bestk * D_);
    float2 v = __ldg(&srow[lane]);
    float2* orow = reinterpret_cast<float2*>(out + (size_t)row * D_);
    orow[lane] = v;
}

extern "C" void kernel_launch(void* const* d_in, const int* in_sizes, int n_in,
                              void* d_out, int out_size) {
    const int*   inputs      = (const int*)  d_in[0];  // [32, 512] int32
    const float* pattern_map = (const float*)d_in[1];  // [50000, 8, 256]
    const float* symbols     = (const float*)d_in[2];  // [256, 64]
    // d_in[3] = tau (== 1.0, positive): argmax is invariant under /tau and the
    // straight-through weights are one-hot to fp32 rounding, so tau is unused.
    float* out = (float*)d_out;                        // [32, 512, 512]

    const int threads = 256;                 // 8 warps -> 8 rows per block
    const int blocks  = NROWS / 8;           // 16384
    symbolic_gumbel_kernel<<<blocks, threads>>>(inputs, pattern_map, symbols, out);
}

// round 2
// speedup vs baseline: 1.0024x; 1.0024x over previous
#include <cuda_runtime.h>
#include <cstdint>

// Problem constants (fixed by the reference)
#define B_ 32
#define S_ 512
#define P_ 8
#define K_ 256
#define D_ 64
#define NROWS (B_ * S_ * P_)   // 131072 rows of K=256 logits each

// ---------------------------------------------------------------------------
// JAX threefry2x32, partitionable mode, key = jax.random.key(42) -> (0, 42).
// Per-element 64-bit counter = flat index i (< 2^32, so hi word == 0).
// 32-bit draw = out0 ^ out1.
//
// Round optimized for sm_103a pipe balance:
//   rotl(x,r) == lo|hi of the widening multiply x * 2^r  (IMAD.WIDE.U32, fma pipe)
//   (lo|hi)^x0 fuses into a single LOP3                  (alu pipe)
// so each round costs 1 alu (LOP3) + 1 fma (IMAD.WIDE) + 1 add (either pipe)
// instead of 2 alu (SHF+LOP3) + 1 add.
// ---------------------------------------------------------------------------
__device__ __forceinline__ void tf_round(uint32_t& x0, uint32_t& x1, int r) {
    x0 += x1;
    unsigned long long w = (unsigned long long)x1 * (1u << r);  // IMAD.WIDE.U32
    uint32_t lo = (uint32_t)w;
    uint32_t hi = (uint32_t)(w >> 32);
    x1 = (lo | hi) ^ x0;  // single LOP3
}

__device__ __forceinline__ uint32_t threefry_bits(uint32_t i) {
    const uint32_t ks0 = 0u;
    const uint32_t ks1 = 42u;
    const uint32_t ks2 = 0x1BD11BDAu ^ 0u ^ 42u;
    uint32_t x0 = 0u + ks0;   // counts_hi + ks0
    uint32_t x1 = i + ks1;    // counts_lo + ks1

    tf_round(x0, x1, 13); tf_round(x0, x1, 15); tf_round(x0, x1, 26); tf_round(x0, x1, 6);
    x0 += ks1; x1 += ks2 + 1u;
    tf_round(x0, x1, 17); tf_round(x0, x1, 29); tf_round(x0, x1, 16); tf_round(x0, x1, 24);
    x0 += ks2; x1 += ks0 + 2u;
    tf_round(x0, x1, 13); tf_round(x0, x1, 15); tf_round(x0, x1, 26); tf_round(x0, x1, 6);
    x0 += ks0; x1 += ks1 + 3u;
    tf_round(x0, x1, 17); tf_round(x0, x1, 29); tf_round(x0, x1, 16); tf_round(x0, x1, 24);
    x0 += ks1; x1 += ks2 + 4u;
    tf_round(x0, x1, 13); tf_round(x0, x1, 15); tf_round(x0, x1, 26); tf_round(x0, x1, 6);
    x0 += ks2; x1 += ks0 + 5u;

    return x0 ^ x1;
}

// jax.random.uniform(minval=tiny) -> gumbel, matching _uniform + _gumbel in fp32
__device__ __forceinline__ float gumbel_from_bits(uint32_t bits) {
    float f = __uint_as_float((bits >> 9) | 0x3f800000u) - 1.0f;  // [0, 1)
    float u = fmaxf(f, 1.17549435e-38f);                          // minval = tiny
    return -logf(-logf(u));
}

// ---------------------------------------------------------------------------
// One warp per (b, s, p) row:
//   cat = inputs[b*S+s]; logits[k] = pattern_map[cat, p, k] + gumbel(flat_idx)
//   k* = argmax (first-max tie-break, matching jnp.argmax)
//   out[row, :] = symbols[k*, :]   (straight-through weights == one_hot to fp32 rounding)
// ---------------------------------------------------------------------------
__global__ void __launch_bounds__(256) symbolic_gumbel_kernel(
    const int*   __restrict__ inputs,       // [B, S] int32
    const float* __restrict__ pattern_map,  // [N_CAT, P, K]
    const float* __restrict__ symbols,      // [K, D]
    float*       __restrict__ out)          // [B, S, P*D]
{
    const int warp = (blockIdx.x * blockDim.x + threadIdx.x) >> 5;
    const int lane = threadIdx.x & 31;
    if (warp >= NROWS) return;

    const int row = warp;
    const int bs  = row >> 3;   // row / P_
    const int p   = row & 7;    // row % P_
    const int cat = __ldg(&inputs[bs]);

    const float* erow = pattern_map + ((size_t)cat * P_ + p) * K_;

    // Each lane owns k in [lane*8, lane*8+8): contiguous float4 loads, and the
    // flat PRNG counter base for this row is row*K_.
    const uint32_t base = (uint32_t)row * (uint32_t)K_ + (uint32_t)(lane * 8);

    const float4* e4 = reinterpret_cast<const float4*>(erow + lane * 8);
    float4 ea = __ldg(&e4[0]);
    float4 eb = __ldg(&e4[1]);
    float e[8] = {ea.x, ea.y, ea.z, ea.w, eb.x, eb.y, eb.z, eb.w};

    float best  = __int_as_float(0xff800000);  // -inf
    int   bestk = 0;
#pragma unroll
    for (int j = 0; j < 8; j++) {
        float g = gumbel_from_bits(threefry_bits(base + (uint32_t)j));
        float x = e[j] + g;
        // strict '>' keeps the first (lowest-k) max within the lane,
        // and k is ascending in j
        if (x > best) { best = x; bestk = lane * 8 + j; }
    }

    // Warp argmax reduction with first-index tie-break
#pragma unroll
    for (int off = 16; off > 0; off >>= 1) {
        float ob = __shfl_xor_sync(0xffffffffu, best, off);
        int   ok = __shfl_xor_sync(0xffffffffu, bestk, off);
        if (ob > best || (ob == best && ok < bestk)) { best = ob; bestk = ok; }
    }
    // all lanes agree on bestk now

    // Copy symbols[bestk, :] (64 floats = 256B) to out[row, :], 2 floats/lane
    const float2* srow = reinterpret_cast<const float2*>(symbols + (size_t)bestk * D_);
    float2 v = __ldg(&srow[lane]);
    float2* orow = reinterpret_cast<float2*>(out + (size_t)row * D_);
    orow[lane] = v;
}

extern "C" void kernel_launch(void* const* d_in, const int* in_sizes, int n_in,
                              void* d_out, int out_size) {
    const int*   inputs      = (const int*)  d_in[0];  // [32, 512] int32
    const float* pattern_map = (const float*)d_in[1];  // [50000, 8, 256]
    const float* symbols     = (const float*)d_in[2];  // [256, 64]
    // d_in[3] = tau (== 1.0, positive): argmax is invariant under /tau and the
    // straight-through weights are one-hot to fp32 rounding, so tau is unused.
    float* out = (float*)d_out;                        // [32, 512, 512]

    const int threads = 256;                 // 8 warps -> 8 rows per block
    const int blocks  = NROWS / 8;           // 16384
    symbolic_gumbel_kernel<<<blocks, threads>>>(inputs, pattern_map, symbols, out);
}